// round 15
// baseline (speedup 1.0000x reference)
#include <cuda_runtime.h>
#include <math.h>

#define Bx 16
#define Tt 32
#define Nn 24
#define Kk 512
#define Hh 128
#define Vv 32000
#define NEGV -1000000000.0f
#define EPSV 1e-38f

#define GROUP 9
#define GRID (Bx*GROUP)     // 144 CTAs, one 9-CTA group per batch
#define NT 768
#define NW (NT/32)
#define ETN (Nn*Nn*Nn)
#define CMAX 48
#define UMAX 4

// ---------------- device scratch ----------------
__device__ __align__(16) float g_beta [Bx*Nn*Tt*Tt];   // [b][n][i][j]
__device__ __align__(16) float g_betaT[Bx*Nn*Tt*Tt];   // [b][n][j][i]
__device__ __align__(16) float g_aL [Bx*Nn*Tt*Tt];     // [b][n][i][j]
__device__ __align__(16) float g_aRT[Bx*Nn*Tt*Tt];     // [b][n][j][i]
__device__ __align__(16) float g_et [ETN];              // [x][y][z]
__device__ float g_tm;
__device__ __align__(16) float g_pnt[Bx*Tt*Nn];
__device__ __align__(128) unsigned g_cnts[Bx*32];       // one padded counter per batch

__device__ __forceinline__ int bidx(int b, int n, int i, int j) {
    return ((b*Nn + n)*Tt + i)*Tt + j;
}

// FMA-pipe log for the throughput-bound mask epilogue only
__device__ __forceinline__ float flogf(float x) {
    int ix = __float_as_int(x);
    int e = ((ix >> 23) & 0xFF) - 127;
    float m = __int_as_float((ix & 0x7FFFFF) | 0x3F800000);  // [1,2)
    if (m > 1.41421356f) { m *= 0.5f; e++; }
    float r = m - 1.0f;
    float z = r * r;
    float p = 7.0376836292E-2f;
    p = fmaf(p, r, -1.1514610310E-1f);
    p = fmaf(p, r,  1.1676998740E-1f);
    p = fmaf(p, r, -1.2420140846E-1f);
    p = fmaf(p, r,  1.4249322787E-1f);
    p = fmaf(p, r, -1.6668057665E-1f);
    p = fmaf(p, r,  2.0000714765E-1f);
    p = fmaf(p, r, -2.4999993993E-1f);
    p = fmaf(p, r,  3.3333331174E-1f);
    float y = r * z * p;
    float fe = (float)e;
    y = fmaf(fe, -2.12194440e-4f, y);
    y = fmaf(-0.5f, z, y);
    return fmaf(fe, 0.693359375f, r + y);
}

// ---------------- init ----------------
__global__ void fill_kernel() {
    int idx = blockIdx.x*blockDim.x + threadIdx.x;
    if (idx < Bx) g_cnts[idx*32] = 0u;
    if (idx < Bx*Nn*Tt*Tt) {
        g_beta [idx] = NEGV;
        g_betaT[idx] = NEGV;
        int j = idx & 31;
        int i = (idx >> 5) & 31;
        int n = (idx >> 10) % Nn;
        g_aL[idx]  = (n == 0 && i == 0 && j == Tt-1) ? 0.0f : NEGV;
        g_aRT[idx] = NEGV;
    }
}

// ---------------- theta prep ----------------
__global__ void theta_kernel(const float* __restrict__ Theta) {
    __shared__ float wmax[18];
    __shared__ float tm_s;
    int tid = threadIdx.x;              // 576
    const float* row = Theta + tid*Nn;
    float m = -3.4e38f;
    #pragma unroll
    for (int z = 0; z < Nn; z++) m = fmaxf(m, row[z]);
    float s = 0.f;
    #pragma unroll
    for (int z = 0; z < Nn; z++) s += expf(row[z] - m);
    float L = m + logf(s);
    float rm = m - L;
    #pragma unroll
    for (int off = 16; off > 0; off >>= 1)
        rm = fmaxf(rm, __shfl_xor_sync(0xffffffffu, rm, off));
    if ((tid & 31) == 0) wmax[tid >> 5] = rm;
    __syncthreads();
    if (tid == 0) {
        float t = -3.4e38f;
        for (int w = 0; w < 18; w++) t = fmaxf(t, wmax[w]);
        tm_s = t; g_tm = t;
    }
    __syncthreads();
    float tm = tm_s;
    for (int z = 0; z < Nn; z++) {
        g_et[tid*Nn + z] = expf(row[z] - L - tm);
    }
}

// ---------------- frontend ----------------
__global__ void frontend_kernel(const float* __restrict__ g_seq,
                                const float* __restrict__ ln_g,
                                const float* __restrict__ ln_b,
                                const float* __restrict__ W1,
                                const float* __restrict__ b1,
                                const float* __restrict__ W2,
                                const float* __restrict__ b2) {
    __shared__ float gs[Kk];
    __shared__ float red[Hh];
    __shared__ float hs[Hh];
    __shared__ float outs[Nn];
    int tid = threadIdx.x;              // 128
    int t = blockIdx.x, b = blockIdx.y;
    const float* row = g_seq + (b*Tt + t)*Kk;

    float v0 = row[tid], v1 = row[tid+128], v2 = row[tid+256], v3 = row[tid+384];
    gs[tid] = v0; gs[tid+128] = v1; gs[tid+256] = v2; gs[tid+384] = v3;

    red[tid] = v0+v1+v2+v3; __syncthreads();
    for (int off = 64; off > 0; off >>= 1) { if (tid < off) red[tid] += red[tid+off]; __syncthreads(); }
    float mu = red[0] * (1.f/512.f);
    __syncthreads();
    red[tid] = v0*v0 + v1*v1 + v2*v2 + v3*v3; __syncthreads();
    for (int off = 64; off > 0; off >>= 1) { if (tid < off) red[tid] += red[tid+off]; __syncthreads(); }
    float var = red[0] * (1.f/512.f) - mu*mu;
    float rstd = rsqrtf(var + 1e-5f);
    __syncthreads();

    #pragma unroll
    for (int q = 0; q < 4; q++) {
        int k = tid + q*128;
        gs[k] = (gs[k] - mu) * rstd * ln_g[k] + ln_b[k];
    }
    __syncthreads();

    float acc = b1[tid];
    for (int k = 0; k < Kk; k++) acc = fmaf(gs[k], W1[k*Hh + tid], acc);
    hs[tid] = 0.5f * acc * (1.0f + erff(acc * 0.70710678118654752440f));
    __syncthreads();

    if (tid < Nn) {
        float o = b2[tid];
        for (int m2 = 0; m2 < Hh; m2++) o = fmaf(hs[m2], W2[m2*Nn + tid], o);
        outs[tid] = o;
    }
    __syncthreads();
    if (tid < Nn) {
        float m = -3.4e38f;
        #pragma unroll
        for (int n = 0; n < Nn; n++) m = fmaxf(m, outs[n]);
        float s = 0.f;
        #pragma unroll
        for (int n = 0; n < Nn; n++) s += expf(outs[n] - m);
        float val = outs[tid] - m - logf(s);
        g_beta [bidx(b, tid, t, t)] = val;
        g_betaT[bidx(b, tid, t, t)] = val;
    }
}

// ---------------- per-batch group barrier (9 CTAs, L2 scope) ----------------
__device__ __forceinline__ void group_bar(unsigned gen, int b) {
    __syncthreads();
    if (threadIdx.x == 0) {
        unsigned prev;
        unsigned* cnt = &g_cnts[b*32];
        asm volatile("atom.acq_rel.gpu.global.add.u32 %0, [%1], %2;"
                     : "=r"(prev) : "l"(cnt), "r"(1u) : "memory");
        if (prev != gen*GROUP - 1u) {
            unsigned v;
            do {
                asm volatile("ld.acquire.gpu.global.u32 %0, [%1];"
                             : "=r"(v) : "l"(cnt) : "memory");
            } while (v < gen*GROUP);
        }
    }
    __syncthreads();
}

__device__ __forceinline__ float lse2(float a, float b) {
    float mx = fmaxf(a, b), mn = fminf(a, b);
    return mx + __logf(1.f + __expf(mn - mx));
}

// ---------------- fused DP kernel: 9-CTA group per batch ----------------
__global__ void __launch_bounds__(NT, 1) dp_kernel() {
    extern __shared__ float sm[];
    float* s_et = sm;                     // ETN (13824)
    float* sA   = s_et + ETN;             // Nn*CMAX (left, exp'd)
    float* sB   = sA + Nn*CMAX;           // Nn*CMAX (right, exp'd)
    float* sC   = sB + Nn*CMAX;           // Nn*CMAX (inside scores)
    float* mA   = sC + Nn*CMAX;           // CMAX
    float* mB   = mA + CMAX;              // CMAX
    float* sEA  = mB + CMAX;              // UMAX*Nn
    float* sMA  = sEA + UMAX*Nn;          // 4
    float* sH   = sMA + 4;                // UMAX*576  H[u][y][z]
    float* sHT  = sH + UMAX*576;          // UMAX*576  H[u][z][y]

    int tid  = threadIdx.x;
    int wid  = tid >> 5;
    int lane = tid & 31;
    int b    = blockIdx.x / GROUP;        // batch for this group
    int lr   = blockIdx.x - b*GROUP;      // rank within group (0..8)

    for (int t = tid; t < ETN; t += NT) s_et[t] = g_et[t];
    __syncthreads();
    float tm = g_tm;
    unsigned bar = 0;

    // ================= INSIDE =================
    for (int l = 2; l <= Tt; l++) {
        int P = Tt - l + 1, S = l - 1;
        int u0, nu, xa, xb;
        if (P >= GROUP) {
            int q = P / GROUP, r = P % GROUP;
            nu = q + (lr < r ? 1 : 0);
            u0 = lr*q + (lr < r ? lr : r);
            xa = 0; xb = Nn;
        } else {
            int R = GROUP / P;
            if (lr < P * R) {
                u0 = lr / R; nu = 1;
                int sl = lr % R;
                int ch = (Nn + R - 1) / R;
                xa = sl * ch; xb = min(Nn, xa + ch);
                if (xa >= xb) nu = 0;
            } else { u0 = 0; nu = 0; xa = xb = 0; }
        }
        int C = nu * S;
        if (nu > 0) {
            // fused stage + max + exp: one thread per column
            for (int c = tid; c < C; c += NT) {
                int u = c / S, s = c - u*S;
                int i = u0 + u;
                const float* pl = &g_beta [bidx(b, 0, i, i+s)];
                const float* pr = &g_betaT[bidx(b, 0, i+l-1, i+s+1)];
                float v[Nn];
                #pragma unroll
                for (int y = 0; y < Nn; y++) v[y] = __ldcg(pl + y*Tt*Tt);
                float m = -3.4e38f;
                #pragma unroll
                for (int y = 0; y < Nn; y++) m = fmaxf(m, v[y]);
                mA[c] = m;
                #pragma unroll
                for (int y = 0; y < Nn; y++) sA[y*C + c] = __expf(v[y] - m);
                #pragma unroll
                for (int y = 0; y < Nn; y++) v[y] = __ldcg(pr + y*Tt*Tt);
                m = -3.4e38f;
                #pragma unroll
                for (int y = 0; y < Nn; y++) m = fmaxf(m, v[y]);
                mB[c] = m;
                #pragma unroll
                for (int y = 0; y < Nn; y++) sB[y*C + c] = __expf(v[y] - m);
            }
            __syncthreads();
            int rows = xb - xa;
            if (S >= 16) {
                // warp-per-(u,x): lane = split; contraction + in-warp lse
                for (int it = wid; it < nu*rows; it += NW) {
                    int u = it / rows, xr = it - u*rows;
                    int x = xa + xr;
                    int s = lane;
                    bool act = (s < S);
                    int c = u*S + (act ? s : 0);
                    float sc = -3.4e38f;
                    if (act) {
                        float er_r[Nn];
                        #pragma unroll
                        for (int z = 0; z < Nn; z++) er_r[z] = sB[z*C + c];
                        const float4* et4 = reinterpret_cast<const float4*>(s_et + x*Nn*Nn);
                        float acc0 = 0.f, acc1 = 0.f;
                        #pragma unroll
                        for (int y = 0; y < Nn; y += 2) {
                            float t0 = 0.f, t1 = 0.f, w0 = 0.f, w1 = 0.f;
                            #pragma unroll
                            for (int q4 = 0; q4 < 6; q4++) {
                                float4 e = et4[y*6 + q4];
                                t0 += e.x*er_r[4*q4]   + e.y*er_r[4*q4+1];
                                t1 += e.z*er_r[4*q4+2] + e.w*er_r[4*q4+3];
                                float4 f = et4[(y+1)*6 + q4];
                                w0 += f.x*er_r[4*q4]   + f.y*er_r[4*q4+1];
                                w1 += f.z*er_r[4*q4+2] + f.w*er_r[4*q4+3];
                            }
                            acc0 = fmaf(sA[y*C + c],     t0 + t1, acc0);
                            acc1 = fmaf(sA[(y+1)*C + c], w0 + w1, acc1);
                        }
                        sc = __logf(fmaxf(acc0 + acc1, EPSV)) + mA[c] + mB[c];
                    }
                    float m = sc;
                    #pragma unroll
                    for (int off = 16; off > 0; off >>= 1)
                        m = fmaxf(m, __shfl_xor_sync(0xffffffffu, m, off));
                    float e = act ? __expf(sc - m) : 0.f;
                    #pragma unroll
                    for (int off = 16; off > 0; off >>= 1)
                        e += __shfl_xor_sync(0xffffffffu, e, off);
                    if (lane == 0) {
                        int i = u0 + u;
                        float val = m + __logf(e) + tm;
                        __stcg(&g_beta [bidx(b, x, i, i+l-1)], val);
                        __stcg(&g_betaT[bidx(b, x, i+l-1, i)], val);
                    }
                }
            } else {
                for (int it = tid; it < rows*C; it += NT) {
                    int x = xa + it / C, c = it % C;
                    float er_r[Nn];
                    #pragma unroll
                    for (int z = 0; z < Nn; z++) er_r[z] = sB[z*C + c];
                    const float4* et4 = reinterpret_cast<const float4*>(s_et + x*Nn*Nn);
                    float acc0 = 0.f, acc1 = 0.f;
                    #pragma unroll
                    for (int y = 0; y < Nn; y += 2) {
                        float t0 = 0.f, t1 = 0.f, w0 = 0.f, w1 = 0.f;
                        #pragma unroll
                        for (int q4 = 0; q4 < 6; q4++) {
                            float4 e = et4[y*6 + q4];
                            t0 += e.x*er_r[4*q4]   + e.y*er_r[4*q4+1];
                            t1 += e.z*er_r[4*q4+2] + e.w*er_r[4*q4+3];
                            float4 f = et4[(y+1)*6 + q4];
                            w0 += f.x*er_r[4*q4]   + f.y*er_r[4*q4+1];
                            w1 += f.z*er_r[4*q4+2] + f.w*er_r[4*q4+3];
                        }
                        acc0 = fmaf(sA[y*C + c],     t0 + t1, acc0);
                        acc1 = fmaf(sA[(y+1)*C + c], w0 + w1, acc1);
                    }
                    float acc = acc0 + acc1;
                    sC[(x - xa)*C + c] = __logf(fmaxf(acc, EPSV)) + mA[c] + mB[c];
                }
                __syncthreads();
                for (int t = tid; t < nu*rows; t += NT) {
                    int u = t / rows, xr = t - u*rows;
                    int i = u0 + u;
                    float m = -3.4e38f;
                    for (int s = 0; s < S; s++) m = fmaxf(m, sC[xr*C + u*S + s]);
                    float sum = 0.f;
                    for (int s = 0; s < S; s++) sum += __expf(sC[xr*C + u*S + s] - m);
                    float val = m + __logf(sum) + tm;
                    __stcg(&g_beta [bidx(b, xa + xr, i, i+l-1)], val);
                    __stcg(&g_betaT[bidx(b, xa + xr, i+l-1, i)], val);
                }
            }
        }
        if (l < Tt) group_bar(++bar, b);   // outside l=Tt reads only lengths < Tt
    }

    // ================= OUTSIDE (H-factored; cL + cR; dual alpha buffers) =====
    for (int l = Tt; l >= 2; l--) {
        int P = Tt - l + 1, S = l - 1;
        int u0, nu, xa, xb;
        if (P >= GROUP) {
            int q = P / GROUP, r = P % GROUP;
            nu = q + (lr < r ? 1 : 0);
            u0 = lr*q + (lr < r ? lr : r);
            xa = 0; xb = Nn;
        } else {
            int R = GROUP / P;
            if (lr < P * R) {
                u0 = lr / R; nu = 1;
                int sl = lr % R;
                int ch = (Nn + R - 1) / R;
                xa = sl * ch; xb = min(Nn, xa + ch);
                if (xa >= xb) nu = 0;
            } else { u0 = 0; nu = 0; xa = xb = 0; }
        }
        int C = nu * S;
        if (nu > 0) {
            int Cw = (C + 31) & ~31;      // warp-aligned column count
            int wH = Cw >> 5;             // first warp handling sEA units
            // phase 1: stage beta columns (thread-per-column; right via betaT)
            // + fused sEA pipeline in spare warps
            if (tid < Cw) {
                for (int c = tid; c < C; c += Cw) {
                    int u = c / S, s = c - u*S;
                    int i = u0 + u;
                    const float* pl = &g_beta [bidx(b, 0, i, i+s)];
                    const float* pr = &g_betaT[bidx(b, 0, i+l-1, i+s+1)];
                    float v[Nn];
                    #pragma unroll
                    for (int y = 0; y < Nn; y++) v[y] = __ldcg(pl + y*Tt*Tt);
                    float m = -3.4e38f;
                    #pragma unroll
                    for (int y = 0; y < Nn; y++) m = fmaxf(m, v[y]);
                    mB[c] = m;            // left-beta max
                    #pragma unroll
                    for (int y = 0; y < Nn; y++) sA[y*C + c] = __expf(v[y] - m);
                    #pragma unroll
                    for (int y = 0; y < Nn; y++) v[y] = __ldcg(pr + y*Tt*Tt);
                    m = -3.4e38f;
                    #pragma unroll
                    for (int y = 0; y < Nn; y++) m = fmaxf(m, v[y]);
                    mA[c] = m;            // right-beta max
                    #pragma unroll
                    for (int y = 0; y < Nn; y++) sB[y*C + c] = __expf(v[y] - m);
                }
            } else if (wid >= wH && wid < wH + nu) {
                int u = wid - wH;
                int i = u0 + u;
                float v = -3.4e38f;
                if (lane < Nn)
                    v = lse2(__ldcg(&g_aL [bidx(b, lane, i, i+l-1)]),
                             __ldcg(&g_aRT[bidx(b, lane, i+l-1, i)]));
                float m = v;
                #pragma unroll
                for (int off = 16; off > 0; off >>= 1)
                    m = fmaxf(m, __shfl_xor_sync(0xffffffffu, m, off));
                if (lane == 0) sMA[u] = m;
                if (lane < Nn) sEA[u*Nn + lane] = __expf(v - m);
            }
            __syncthreads();
            // H[u][y][z] = sum_x ea[u][x] * et[x][y][z]
            for (int t = tid; t < nu*576; t += NT) {
                int u = t / 576, yz = t - u*576;
                float h = 0.f;
                #pragma unroll
                for (int x = 0; x < Nn; x++)
                    h = fmaf(sEA[u*Nn + x], s_et[x*576 + yz], h);
                int y = yz / Nn, z = yz - (yz/Nn)*Nn;
                sH [u*576 + yz]       = h;
                sHT[u*576 + z*Nn + y] = h;
            }
            __syncthreads();
            int rows = xb - xa;
            // cL[y,c] = sum_z H[u][y][z] * erb[z,c]
            for (int it = tid; it < rows*C; it += NT) {
                int y = xa + it / C, c = it % C;
                int u = c / S, s = c - u*S;
                float erb_r[Nn];
                #pragma unroll
                for (int z = 0; z < Nn; z++) erb_r[z] = sB[z*C + c];
                const float4* h4 = reinterpret_cast<const float4*>(sH + u*576 + y*Nn);
                float t0 = 0.f, t1 = 0.f;
                #pragma unroll
                for (int q4 = 0; q4 < 6; q4++) {
                    float4 e = h4[q4];
                    t0 += e.x*erb_r[4*q4]   + e.y*erb_r[4*q4+1];
                    t1 += e.z*erb_r[4*q4+2] + e.w*erb_r[4*q4+3];
                }
                float acc = t0 + t1;
                int i = u0 + u;
                float val = __logf(fmaxf(acc, EPSV)) + tm + sMA[u] + mA[c];
                float* cell = &g_aL[bidx(b, y, i, i+s)];
                __stcg(cell, lse2(__ldcg(cell), val));
            }
            // cR[z,c] = sum_y H[u][y][z] * elb[y,c]  (via HT[u][z][y])
            for (int it = tid; it < rows*C; it += NT) {
                int z = xa + it / C, c = it % C;
                int u = c / S, s = c - u*S;
                float elb_r[Nn];
                #pragma unroll
                for (int y = 0; y < Nn; y++) elb_r[y] = sA[y*C + c];
                const float4* h4 = reinterpret_cast<const float4*>(sHT + u*576 + z*Nn);
                float t0 = 0.f, t1 = 0.f;
                #pragma unroll
                for (int q4 = 0; q4 < 6; q4++) {
                    float4 e = h4[q4];
                    t0 += e.x*elb_r[4*q4]   + e.y*elb_r[4*q4+1];
                    t1 += e.z*elb_r[4*q4+2] + e.w*elb_r[4*q4+3];
                }
                float acc = t0 + t1;
                int i = u0 + u;
                float val = __logf(fmaxf(acc, EPSV)) + tm + sMA[u] + mB[c];
                float* cell = &g_aRT[bidx(b, z, i+l-1, i+s+1)];
                __stcg(cell, lse2(__ldcg(cell), val));
            }
        }
        if (l > 2) group_bar(++bar, b);
    }
}

// ---------------- p_nt ----------------
__global__ void pnt_kernel() {
    int b = blockIdx.x;
    int tid = threadIdx.x;               // 768
    int n = tid / Tt, t = tid % Tt;
    float logZ = g_beta[bidx(b, 0, 0, Tt-1)];
    int d = bidx(b, n, t, t);
    float a = lse2(g_aL[d], g_aRT[d]);
    g_pnt[(b*Tt + t)*Nn + n] = __expf(a + g_beta[d] - logZ);
}

// ---------------- L_pcfg ----------------
__global__ void lpcfg_kernel(float* __restrict__ out) {
    int tid = threadIdx.x;               // 32
    float v = (tid < Bx) ? g_beta[bidx(tid, 0, 0, Tt-1)] : 0.f;
    #pragma unroll
    for (int off = 16; off > 0; off >>= 1) v += __shfl_xor_sync(0xffffffffu, v, off);
    if (tid == 0) out[(long long)Bx*Tt*Vv] = -v / (float)Bx;
}

// ---------------- mask_logits ----------------
__global__ void mask_kernel(const float* __restrict__ voc, float* __restrict__ out) {
    extern __shared__ float sm[];
    float* voc_s = sm;                   // 24*128
    float* pn_s  = sm + Nn*128;          // 512*24
    int tid = threadIdx.x;               // 256
    int v0 = blockIdx.x * 128;

    for (int t = tid; t < Bx*Tt*Nn; t += 256) pn_s[t] = g_pnt[t];
    for (int t = tid; t < Nn*128; t += 256) {
        int n = t >> 7, vl = t & 127;
        voc_s[t] = voc[n*Vv + v0 + vl];
    }
    __syncthreads();

    int vl = tid & 127;
    int v = v0 + vl;
    for (int bt = tid >> 7; bt < Bx*Tt; bt += 2) {
        float acc = 1e-6f;
        const float* p = pn_s + bt*Nn;
        #pragma unroll
        for (int n = 0; n < Nn; n++) acc = fmaf(p[n], voc_s[n*128 + vl], acc);
        out[(long long)bt*Vv + v] = flogf(acc);
    }
}

// ---------------- launch ----------------
extern "C" void kernel_launch(void* const* d_in, const int* in_sizes, int n_in,
                              void* d_out, int out_size) {
    const float* g_seq   = (const float*)d_in[0];
    const float* Theta   = (const float*)d_in[1];
    const float* nt2voc  = (const float*)d_in[2];
    const float* ln_g    = (const float*)d_in[3];
    const float* ln_b    = (const float*)d_in[4];
    const float* W1      = (const float*)d_in[5];
    const float* b1      = (const float*)d_in[6];
    const float* W2      = (const float*)d_in[7];
    const float* b2      = (const float*)d_in[8];
    float* out = (float*)d_out;

    const int MASK_SMEM = (Nn*128 + Bx*Tt*Nn) * 4;
    const int DP_SMEM   = (ETN + 3*Nn*CMAX + 2*CMAX + UMAX*Nn + 4 + 2*UMAX*576) * 4;
    cudaFuncSetAttribute(mask_kernel, cudaFuncAttributeMaxDynamicSharedMemorySize, MASK_SMEM);
    cudaFuncSetAttribute(dp_kernel,   cudaFuncAttributeMaxDynamicSharedMemorySize, DP_SMEM);

    fill_kernel<<<(Bx*Nn*Tt*Tt + 255)/256, 256>>>();
    theta_kernel<<<1, 576>>>(Theta);
    frontend_kernel<<<dim3(Tt, Bx), 128>>>(g_seq, ln_g, ln_b, W1, b1, W2, b2);

    dp_kernel<<<GRID, NT, DP_SMEM>>>();

    pnt_kernel<<<Bx, Nn*Tt>>>();
    lpcfg_kernel<<<1, 32>>>(out);
    mask_kernel<<<Vv/128, 256, MASK_SMEM>>>(nt2voc, out);
}

// round 16
// speedup vs baseline: 1.0646x; 1.0646x over previous
#include <cuda_runtime.h>
#include <math.h>

#define Bx 16
#define Tt 32
#define Nn 24
#define Kk 512
#define Hh 128
#define Vv 32000
#define NEGV -1000000000.0f
#define EPSV 1e-38f

#define GROUP 9
#define GRID (Bx*GROUP)     // 144 CTAs, one 9-CTA group per batch
#define NT 768
#define ETN (Nn*Nn*Nn)
#define CMAX 48
#define UMAX 4

// ---------------- device scratch ----------------
__device__ __align__(16) float g_beta [Bx*Nn*Tt*Tt];   // [b][n][i][j]
__device__ __align__(16) float g_betaT[Bx*Nn*Tt*Tt];   // [b][n][j][i]
__device__ __align__(16) float g_aL [Bx*Nn*Tt*Tt];     // [b][n][i][j]
__device__ __align__(16) float g_aRT[Bx*Nn*Tt*Tt];     // [b][n][j][i]
__device__ __align__(16) float g_et [ETN];              // [x][y][z]
__device__ float g_tm;
__device__ __align__(16) float g_pnt[Bx*Tt*Nn];
__device__ __align__(128) unsigned g_cnts[Bx*32];       // one padded counter per batch

__device__ __forceinline__ int bidx(int b, int n, int i, int j) {
    return ((b*Nn + n)*Tt + i)*Tt + j;
}

// ---------------- packed f32x2 helpers (sm_103a) ----------------
__device__ __forceinline__ unsigned long long pk2(float lo, float hi) {
    unsigned long long r;
    asm("mov.b64 %0, {%1, %2};" : "=l"(r) : "f"(lo), "f"(hi));
    return r;
}
__device__ __forceinline__ float2 upk2(unsigned long long v) {
    float2 r;
    asm("mov.b64 {%0, %1}, %2;" : "=f"(r.x), "=f"(r.y) : "l"(v));
    return r;
}
__device__ __forceinline__ unsigned long long ffma2(unsigned long long a,
                                                    unsigned long long b,
                                                    unsigned long long c) {
    unsigned long long d;
    asm("fma.rn.f32x2 %0, %1, %2, %3;" : "=l"(d) : "l"(a), "l"(b), "l"(c));
    return d;
}

// ---------------- init ----------------
__global__ void fill_kernel() {
    int idx = blockIdx.x*blockDim.x + threadIdx.x;
    if (idx < Bx) g_cnts[idx*32] = 0u;
    if (idx < Bx*Nn*Tt*Tt) {
        g_beta [idx] = NEGV;
        g_betaT[idx] = NEGV;
        int j = idx & 31;
        int i = (idx >> 5) & 31;
        int n = (idx >> 10) % Nn;
        g_aL[idx]  = (n == 0 && i == 0 && j == Tt-1) ? 0.0f : NEGV;
        g_aRT[idx] = NEGV;
    }
}

// ---------------- theta prep ----------------
__global__ void theta_kernel(const float* __restrict__ Theta) {
    __shared__ float wmax[18];
    __shared__ float tm_s;
    int tid = threadIdx.x;              // 576
    const float* row = Theta + tid*Nn;
    float m = -3.4e38f;
    #pragma unroll
    for (int z = 0; z < Nn; z++) m = fmaxf(m, row[z]);
    float s = 0.f;
    #pragma unroll
    for (int z = 0; z < Nn; z++) s += expf(row[z] - m);
    float L = m + logf(s);
    float rm = m - L;
    #pragma unroll
    for (int off = 16; off > 0; off >>= 1)
        rm = fmaxf(rm, __shfl_xor_sync(0xffffffffu, rm, off));
    if ((tid & 31) == 0) wmax[tid >> 5] = rm;
    __syncthreads();
    if (tid == 0) {
        float t = -3.4e38f;
        for (int w = 0; w < 18; w++) t = fmaxf(t, wmax[w]);
        tm_s = t; g_tm = t;
    }
    __syncthreads();
    float tm = tm_s;
    for (int z = 0; z < Nn; z++) {
        g_et[tid*Nn + z] = expf(row[z] - L - tm);
    }
}

// ---------------- frontend ----------------
__global__ void frontend_kernel(const float* __restrict__ g_seq,
                                const float* __restrict__ ln_g,
                                const float* __restrict__ ln_b,
                                const float* __restrict__ W1,
                                const float* __restrict__ b1,
                                const float* __restrict__ W2,
                                const float* __restrict__ b2) {
    __shared__ float gs[Kk];
    __shared__ float red[Hh];
    __shared__ float hs[Hh];
    __shared__ float outs[Nn];
    int tid = threadIdx.x;              // 128
    int t = blockIdx.x, b = blockIdx.y;
    const float* row = g_seq + (b*Tt + t)*Kk;

    float v0 = row[tid], v1 = row[tid+128], v2 = row[tid+256], v3 = row[tid+384];
    gs[tid] = v0; gs[tid+128] = v1; gs[tid+256] = v2; gs[tid+384] = v3;

    red[tid] = v0+v1+v2+v3; __syncthreads();
    for (int off = 64; off > 0; off >>= 1) { if (tid < off) red[tid] += red[tid+off]; __syncthreads(); }
    float mu = red[0] * (1.f/512.f);
    __syncthreads();
    red[tid] = v0*v0 + v1*v1 + v2*v2 + v3*v3; __syncthreads();
    for (int off = 64; off > 0; off >>= 1) { if (tid < off) red[tid] += red[tid+off]; __syncthreads(); }
    float var = red[0] * (1.f/512.f) - mu*mu;
    float rstd = rsqrtf(var + 1e-5f);
    __syncthreads();

    #pragma unroll
    for (int q = 0; q < 4; q++) {
        int k = tid + q*128;
        gs[k] = (gs[k] - mu) * rstd * ln_g[k] + ln_b[k];
    }
    __syncthreads();

    float acc = b1[tid];
    for (int k = 0; k < Kk; k++) acc = fmaf(gs[k], W1[k*Hh + tid], acc);
    hs[tid] = 0.5f * acc * (1.0f + erff(acc * 0.70710678118654752440f));
    __syncthreads();

    if (tid < Nn) {
        float o = b2[tid];
        for (int m2 = 0; m2 < Hh; m2++) o = fmaf(hs[m2], W2[m2*Nn + tid], o);
        outs[tid] = o;
    }
    __syncthreads();
    if (tid < Nn) {
        float m = -3.4e38f;
        #pragma unroll
        for (int n = 0; n < Nn; n++) m = fmaxf(m, outs[n]);
        float s = 0.f;
        #pragma unroll
        for (int n = 0; n < Nn; n++) s += expf(outs[n] - m);
        float val = outs[tid] - m - logf(s);
        g_beta [bidx(b, tid, t, t)] = val;
        g_betaT[bidx(b, tid, t, t)] = val;
    }
}

// ---------------- per-batch group barrier (9 CTAs, L2 scope) ----------------
__device__ __forceinline__ void group_bar(unsigned gen, int b) {
    __syncthreads();
    if (threadIdx.x == 0) {
        unsigned prev;
        unsigned* cnt = &g_cnts[b*32];
        asm volatile("atom.acq_rel.gpu.global.add.u32 %0, [%1], %2;"
                     : "=r"(prev) : "l"(cnt), "r"(1u) : "memory");
        if (prev != gen*GROUP - 1u) {
            unsigned v;
            do {
                asm volatile("ld.acquire.gpu.global.u32 %0, [%1];"
                             : "=r"(v) : "l"(cnt) : "memory");
            } while (v < gen*GROUP);
        }
    }
    __syncthreads();
}

__device__ __forceinline__ float lse2(float a, float b) {
    float mx = fmaxf(a, b), mn = fminf(a, b);
    return mx + __logf(1.f + __expf(mn - mx));
}

// ---------------- fused DP kernel: 9-CTA group per batch ----------------
__global__ void __launch_bounds__(NT, 1) dp_kernel() {
    extern __shared__ float sm[];
    float* s_et = sm;                     // ETN (13824)
    float* sA   = s_et + ETN;             // Nn*CMAX (left, exp'd)
    float* sB   = sA + Nn*CMAX;           // Nn*CMAX (right, exp'd)
    float* sC   = sB + Nn*CMAX;           // Nn*CMAX (inside scores)
    float* mA   = sC + Nn*CMAX;           // CMAX
    float* mB   = mA + CMAX;              // CMAX
    float* sEA  = mB + CMAX;              // UMAX*Nn
    float* sMA  = sEA + UMAX*Nn;          // 4
    float* sH   = sMA + 4;                // UMAX*576  H[u][y][z]
    float* sHT  = sH + UMAX*576;          // UMAX*576  H[u][z][y]

    int tid  = threadIdx.x;
    int wid  = tid >> 5;
    int lane = tid & 31;
    int b    = blockIdx.x / GROUP;        // batch for this group
    int lr   = blockIdx.x - b*GROUP;      // rank within group (0..8)

    for (int t = tid; t < ETN; t += NT) s_et[t] = g_et[t];
    __syncthreads();
    float tm = g_tm;
    unsigned bar = 0;

    // ================= INSIDE =================
    for (int l = 2; l <= Tt; l++) {
        int P = Tt - l + 1, S = l - 1;
        int u0, nu, xa, xb;
        if (P >= GROUP) {
            int q = P / GROUP, r = P % GROUP;
            nu = q + (lr < r ? 1 : 0);
            u0 = lr*q + (lr < r ? lr : r);
            xa = 0; xb = Nn;
        } else {
            int R = GROUP / P;
            if (lr < P * R) {
                u0 = lr / R; nu = 1;
                int sl = lr % R;
                int ch = (Nn + R - 1) / R;
                xa = sl * ch; xb = min(Nn, xa + ch);
                if (xa >= xb) nu = 0;
            } else { u0 = 0; nu = 0; xa = xb = 0; }
        }
        int C = nu * S;
        if (nu > 0) {
            // fused stage + max + exp: one thread per column
            for (int c = tid; c < C; c += NT) {
                int u = c / S, s = c - u*S;
                int i = u0 + u;
                const float* pl = &g_beta [bidx(b, 0, i, i+s)];
                const float* pr = &g_betaT[bidx(b, 0, i+l-1, i+s+1)];
                float v[Nn];
                #pragma unroll
                for (int y = 0; y < Nn; y++) v[y] = __ldcg(pl + y*Tt*Tt);
                float m = -3.4e38f;
                #pragma unroll
                for (int y = 0; y < Nn; y++) m = fmaxf(m, v[y]);
                mA[c] = m;
                #pragma unroll
                for (int y = 0; y < Nn; y++) sA[y*C + c] = __expf(v[y] - m);
                #pragma unroll
                for (int y = 0; y < Nn; y++) v[y] = __ldcg(pr + y*Tt*Tt);
                m = -3.4e38f;
                #pragma unroll
                for (int y = 0; y < Nn; y++) m = fmaxf(m, v[y]);
                mB[c] = m;
                #pragma unroll
                for (int y = 0; y < Nn; y++) sB[y*C + c] = __expf(v[y] - m);
            }
            __syncthreads();
            int rows = xb - xa;
            for (int it = tid; it < rows*C; it += NT) {
                int x = xa + it / C, c = it % C;
                // pack right-child exps pairwise over z
                unsigned long long er2[12];
                #pragma unroll
                for (int q = 0; q < 12; q++)
                    er2[q] = pk2(sB[(2*q)*C + c], sB[(2*q+1)*C + c]);
                const ulonglong2* et2 = reinterpret_cast<const ulonglong2*>(s_et + x*Nn*Nn);
                float acc0 = 0.f, acc1 = 0.f;
                #pragma unroll
                for (int y = 0; y < Nn; y += 2) {
                    unsigned long long t2 = 0ull, w2 = 0ull;
                    #pragma unroll
                    for (int q = 0; q < 6; q++) {
                        ulonglong2 ea_ = et2[y*6 + q];
                        t2 = ffma2(ea_.x, er2[2*q],   t2);
                        t2 = ffma2(ea_.y, er2[2*q+1], t2);
                        ulonglong2 eb_ = et2[(y+1)*6 + q];
                        w2 = ffma2(eb_.x, er2[2*q],   w2);
                        w2 = ffma2(eb_.y, er2[2*q+1], w2);
                    }
                    float2 tt = upk2(t2), ww = upk2(w2);
                    acc0 = fmaf(sA[y*C + c],     tt.x + tt.y, acc0);
                    acc1 = fmaf(sA[(y+1)*C + c], ww.x + ww.y, acc1);
                }
                float acc = acc0 + acc1;
                sC[(x - xa)*C + c] = __logf(fmaxf(acc, EPSV)) + mA[c] + mB[c];
            }
            __syncthreads();
            for (int t = tid; t < nu*rows; t += NT) {
                int u = t / rows, xr = t - u*rows;
                int i = u0 + u;
                float m = -3.4e38f;
                for (int s = 0; s < S; s++) m = fmaxf(m, sC[xr*C + u*S + s]);
                float sum = 0.f;
                for (int s = 0; s < S; s++) sum += __expf(sC[xr*C + u*S + s] - m);
                float val = m + __logf(sum) + tm;
                __stcg(&g_beta [bidx(b, xa + xr, i, i+l-1)], val);
                __stcg(&g_betaT[bidx(b, xa + xr, i+l-1, i)], val);
            }
        }
        group_bar(++bar, b);
    }

    // ================= OUTSIDE (H-factored; cL + cR; dual alpha buffers) =====
    for (int l = Tt; l >= 2; l--) {
        int P = Tt - l + 1, S = l - 1;
        int u0, nu, xa, xb;
        if (P >= GROUP) {
            int q = P / GROUP, r = P % GROUP;
            nu = q + (lr < r ? 1 : 0);
            u0 = lr*q + (lr < r ? lr : r);
            xa = 0; xb = Nn;
        } else {
            int R = GROUP / P;
            if (lr < P * R) {
                u0 = lr / R; nu = 1;
                int sl = lr % R;
                int ch = (Nn + R - 1) / R;
                xa = sl * ch; xb = min(Nn, xa + ch);
                if (xa >= xb) nu = 0;
            } else { u0 = 0; nu = 0; xa = xb = 0; }
        }
        int C = nu * S;
        if (nu > 0) {
            int Cw = (C + 31) & ~31;      // warp-aligned column count
            int wH = Cw >> 5;             // first warp handling sEA units
            // phase 1: stage beta columns (thread-per-column; right via betaT)
            // + fused sEA pipeline in spare warps
            if (tid < Cw) {
                for (int c = tid; c < C; c += Cw) {
                    int u = c / S, s = c - u*S;
                    int i = u0 + u;
                    const float* pl = &g_beta [bidx(b, 0, i, i+s)];
                    const float* pr = &g_betaT[bidx(b, 0, i+l-1, i+s+1)];
                    float v[Nn];
                    #pragma unroll
                    for (int y = 0; y < Nn; y++) v[y] = __ldcg(pl + y*Tt*Tt);
                    float m = -3.4e38f;
                    #pragma unroll
                    for (int y = 0; y < Nn; y++) m = fmaxf(m, v[y]);
                    mB[c] = m;            // left-beta max
                    #pragma unroll
                    for (int y = 0; y < Nn; y++) sA[y*C + c] = __expf(v[y] - m);
                    #pragma unroll
                    for (int y = 0; y < Nn; y++) v[y] = __ldcg(pr + y*Tt*Tt);
                    m = -3.4e38f;
                    #pragma unroll
                    for (int y = 0; y < Nn; y++) m = fmaxf(m, v[y]);
                    mA[c] = m;            // right-beta max
                    #pragma unroll
                    for (int y = 0; y < Nn; y++) sB[y*C + c] = __expf(v[y] - m);
                }
            } else if (wid >= wH && wid < wH + nu) {
                int u = wid - wH;
                int i = u0 + u;
                float v = -3.4e38f;
                if (lane < Nn)
                    v = lse2(__ldcg(&g_aL [bidx(b, lane, i, i+l-1)]),
                             __ldcg(&g_aRT[bidx(b, lane, i+l-1, i)]));
                float m = v;
                #pragma unroll
                for (int off = 16; off > 0; off >>= 1)
                    m = fmaxf(m, __shfl_xor_sync(0xffffffffu, m, off));
                if (lane == 0) sMA[u] = m;
                if (lane < Nn) sEA[u*Nn + lane] = __expf(v - m);
            }
            __syncthreads();
            // H[u][y][z] = sum_x ea[u][x] * et[x][y][z]
            for (int t = tid; t < nu*576; t += NT) {
                int u = t / 576, yz = t - u*576;
                float h = 0.f;
                #pragma unroll
                for (int x = 0; x < Nn; x++)
                    h = fmaf(sEA[u*Nn + x], s_et[x*576 + yz], h);
                int y = yz / Nn, z = yz - (yz/Nn)*Nn;
                sH [u*576 + yz]       = h;
                sHT[u*576 + z*Nn + y] = h;
            }
            __syncthreads();
            int rows = xb - xa;
            // cL[y,c] = sum_z H[u][y][z] * erb[z,c]  (packed f32x2)
            for (int it = tid; it < rows*C; it += NT) {
                int y = xa + it / C, c = it % C;
                int u = c / S, s = c - u*S;
                unsigned long long er2[12];
                #pragma unroll
                for (int q = 0; q < 12; q++)
                    er2[q] = pk2(sB[(2*q)*C + c], sB[(2*q+1)*C + c]);
                const ulonglong2* h2 = reinterpret_cast<const ulonglong2*>(sH + u*576 + y*Nn);
                unsigned long long t2 = 0ull;
                #pragma unroll
                for (int q = 0; q < 6; q++) {
                    ulonglong2 e = h2[q];
                    t2 = ffma2(e.x, er2[2*q],   t2);
                    t2 = ffma2(e.y, er2[2*q+1], t2);
                }
                float2 tt = upk2(t2);
                float acc = tt.x + tt.y;
                int i = u0 + u;
                float val = __logf(fmaxf(acc, EPSV)) + tm + sMA[u] + mA[c];
                float* cell = &g_aL[bidx(b, y, i, i+s)];
                __stcg(cell, lse2(__ldcg(cell), val));
            }
            // cR[z,c] = sum_y H[u][y][z] * elb[y,c]  (via HT[u][z][y], packed)
            for (int it = tid; it < rows*C; it += NT) {
                int z = xa + it / C, c = it % C;
                int u = c / S, s = c - u*S;
                unsigned long long el2[12];
                #pragma unroll
                for (int q = 0; q < 12; q++)
                    el2[q] = pk2(sA[(2*q)*C + c], sA[(2*q+1)*C + c]);
                const ulonglong2* h2 = reinterpret_cast<const ulonglong2*>(sHT + u*576 + z*Nn);
                unsigned long long t2 = 0ull;
                #pragma unroll
                for (int q = 0; q < 6; q++) {
                    ulonglong2 e = h2[q];
                    t2 = ffma2(e.x, el2[2*q],   t2);
                    t2 = ffma2(e.y, el2[2*q+1], t2);
                }
                float2 tt = upk2(t2);
                float acc = tt.x + tt.y;
                int i = u0 + u;
                float val = __logf(fmaxf(acc, EPSV)) + tm + sMA[u] + mB[c];
                float* cell = &g_aRT[bidx(b, z, i+l-1, i+s+1)];
                __stcg(cell, lse2(__ldcg(cell), val));
            }
        }
        if (l > 2) group_bar(++bar, b);
    }
}

// ---------------- p_nt ----------------
__global__ void pnt_kernel() {
    int b = blockIdx.x;
    int tid = threadIdx.x;               // 768
    int n = tid / Tt, t = tid % Tt;
    float logZ = g_beta[bidx(b, 0, 0, Tt-1)];
    int d = bidx(b, n, t, t);
    float a = lse2(g_aL[d], g_aRT[d]);
    g_pnt[(b*Tt + t)*Nn + n] = __expf(a + g_beta[d] - logZ);
}

// ---------------- L_pcfg ----------------
__global__ void lpcfg_kernel(float* __restrict__ out) {
    int tid = threadIdx.x;               // 32
    float v = (tid < Bx) ? g_beta[bidx(tid, 0, 0, Tt-1)] : 0.f;
    #pragma unroll
    for (int off = 16; off > 0; off >>= 1) v += __shfl_xor_sync(0xffffffffu, v, off);
    if (tid == 0) out[(long long)Bx*Tt*Vv] = -v / (float)Bx;
}

// ---------------- mask_logits ----------------
__global__ void mask_kernel(const float* __restrict__ voc, float* __restrict__ out) {
    extern __shared__ float sm[];
    float* voc_s = sm;                   // 24*128
    float* pn_s  = sm + Nn*128;          // 512*24
    int tid = threadIdx.x;               // 256
    int v0 = blockIdx.x * 128;

    for (int t = tid; t < Bx*Tt*Nn; t += 256) pn_s[t] = g_pnt[t];
    for (int t = tid; t < Nn*128; t += 256) {
        int n = t >> 7, vl = t & 127;
        voc_s[t] = voc[n*Vv + v0 + vl];
    }
    __syncthreads();

    int vl = tid & 127;
    int v = v0 + vl;
    for (int bt = tid >> 7; bt < Bx*Tt; bt += 2) {
        float acc = 1e-6f;
        const float* p = pn_s + bt*Nn;
        #pragma unroll
        for (int n = 0; n < Nn; n++) acc = fmaf(p[n], voc_s[n*128 + vl], acc);
        out[(long long)bt*Vv + v] = __logf(acc);
    }
}

// ---------------- launch ----------------
extern "C" void kernel_launch(void* const* d_in, const int* in_sizes, int n_in,
                              void* d_out, int out_size) {
    const float* g_seq   = (const float*)d_in[0];
    const float* Theta   = (const float*)d_in[1];
    const float* nt2voc  = (const float*)d_in[2];
    const float* ln_g    = (const float*)d_in[3];
    const float* ln_b    = (const float*)d_in[4];
    const float* W1      = (const float*)d_in[5];
    const float* b1      = (const float*)d_in[6];
    const float* W2      = (const float*)d_in[7];
    const float* b2      = (const float*)d_in[8];
    float* out = (float*)d_out;

    const int MASK_SMEM = (Nn*128 + Bx*Tt*Nn) * 4;
    const int DP_SMEM   = (ETN + 3*Nn*CMAX + 2*CMAX + UMAX*Nn + 4 + 2*UMAX*576) * 4;
    cudaFuncSetAttribute(mask_kernel, cudaFuncAttributeMaxDynamicSharedMemorySize, MASK_SMEM);
    cudaFuncSetAttribute(dp_kernel,   cudaFuncAttributeMaxDynamicSharedMemorySize, DP_SMEM);

    fill_kernel<<<(Bx*Nn*Tt*Tt + 255)/256, 256>>>();
    theta_kernel<<<1, 576>>>(Theta);
    frontend_kernel<<<dim3(Tt, Bx), 128>>>(g_seq, ln_g, ln_b, W1, b1, W2, b2);

    dp_kernel<<<GRID, NT, DP_SMEM>>>();

    pnt_kernel<<<Bx, Nn*Tt>>>();
    lpcfg_kernel<<<1, 32>>>(out);
    mask_kernel<<<Vv/128, 256, MASK_SMEM>>>(nt2voc, out);
}